// round 3
// baseline (speedup 1.0000x reference)
#include <cuda_runtime.h>
#include <cstdint>

#define B_DIM 8
#define R_DIM 128
#define H_DIM 4096
#define W_DIM 4096
#define KSPLIT 4

// Scratch (device globals: allocation-free per harness rules)
__device__ float g_part[KSPLIT * B_DIM * R_DIM * R_DIM]; // 2 MB  partial Gram sums
__device__ float g_Ci[B_DIM * R_DIM * R_DIM];            // 512KB C^-1 per batch
__device__ float g_Pt[B_DIM * R_DIM * W_DIM];            // 16 MB  Pt[b][s][w]

// ---------------------------------------------------------------------------
// K1: partial Gram  part[ks][b][r][s] = sum_{w in ks-split} N[r][w]*N[s][w]
// ---------------------------------------------------------------------------
__global__ void k1_gram(const float* __restrict__ N) {
    __shared__ float As[32][33];
    __shared__ float Bs[32][33];
    int b  = blockIdx.z;
    int ks = blockIdx.y;
    int ti = blockIdx.x & 3, tj = blockIdx.x >> 2;
    int r0 = ti * 32, s0 = tj * 32;
    int tx = threadIdx.x, ty = threadIdx.y;
    int tid = ty * 16 + tx;
    const float* Nb = N + (size_t)b * R_DIM * W_DIM;

    float a00 = 0.f, a01 = 0.f, a10 = 0.f, a11 = 0.f;
    int k_beg = ks * (W_DIM / KSPLIT);
    int k_end = k_beg + (W_DIM / KSPLIT);
    for (int kk = k_beg; kk < k_end; kk += 32) {
        for (int e = tid; e < 1024; e += 256) {
            int i = e >> 5, k = e & 31;
            As[i][k] = Nb[(size_t)(r0 + i) * W_DIM + kk + k];
            Bs[i][k] = Nb[(size_t)(s0 + i) * W_DIM + kk + k];
        }
        __syncthreads();
#pragma unroll
        for (int k = 0; k < 32; k++) {
            float x0 = As[2 * ty][k], x1 = As[2 * ty + 1][k];
            float y0 = Bs[2 * tx][k], y1 = Bs[2 * tx + 1][k];
            a00 += x0 * y0; a01 += x0 * y1; a10 += x1 * y0; a11 += x1 * y1;
        }
        __syncthreads();
    }
    float* P = g_part + ((size_t)(ks * B_DIM + b)) * R_DIM * R_DIM;
    P[(r0 + 2 * ty) * 128 + s0 + 2 * tx]         = a00;
    P[(r0 + 2 * ty) * 128 + s0 + 2 * tx + 1]     = a01;
    P[(r0 + 2 * ty + 1) * 128 + s0 + 2 * tx]     = a10;
    P[(r0 + 2 * ty + 1) * 128 + s0 + 2 * tx + 1] = a11;
}

// ---------------------------------------------------------------------------
// K2: C = alpha*I + 2*gamma*G; in-place Gauss-Jordan inverse (SPD, no pivot)
// ---------------------------------------------------------------------------
__global__ void k2_inv(const float* __restrict__ alpha, const float* __restrict__ gamma) {
    extern __shared__ float sgj[];
    float* M    = sgj;             // 128*129
    float* rowk = M + 128 * 129;   // 128
    float* colk = rowk + 128;      // 128
    __shared__ float s_invp;

    int b = blockIdx.x;
    int tid = threadIdx.x;
    float a  = alpha[b];
    float g2 = 2.0f * gamma[b];

    for (int e = tid; e < 128 * 128; e += 1024) {
        int i = e >> 7, j = e & 127;
        float s = 0.f;
#pragma unroll
        for (int p = 0; p < KSPLIT; p++)
            s += g_part[((size_t)(p * B_DIM + b)) * 16384 + e];
        M[i * 129 + j] = g2 * s + (i == j ? a : 0.f);
    }
    __syncthreads();

    for (int k = 0; k < 128; k++) {
        if (tid < 128) { rowk[tid] = M[k * 129 + tid]; colk[tid] = M[tid * 129 + k]; }
        if (tid == 0)  s_invp = 1.0f / M[k * 129 + k];
        __syncthreads();
        float invp = s_invp;
#pragma unroll
        for (int e0 = 0; e0 < 16; e0++) {
            int e = tid + e0 * 1024;
            int i = e >> 7, j = e & 127;
            float v;
            if (i == k) {
                v = (j == k) ? invp : rowk[j] * invp;
            } else if (j == k) {
                v = -colk[i] * invp;
            } else {
                v = M[i * 129 + j] - colk[i] * rowk[j] * invp;
            }
            M[i * 129 + j] = v;
        }
        __syncthreads();
    }

    float* Ci = g_Ci + (size_t)b * 16384;
    for (int e = tid; e < 16384; e += 1024)
        Ci[e] = M[(e >> 7) * 129 + (e & 127)];
}

// ---------------------------------------------------------------------------
// K3: Pt[b][s][w] = 2*gamma * sum_r Cinv[r][s] * N[r][w]   (stored s-major!)
// ---------------------------------------------------------------------------
__global__ void k3_pt(const float* __restrict__ N, const float* __restrict__ gamma) {
    __shared__ float cs[128][17];
    int b  = blockIdx.z;
    int s0 = blockIdx.y * 16;
    int w  = blockIdx.x * 256 + threadIdx.x;
    const float* Ci = g_Ci + (size_t)b * 16384;
    for (int e = threadIdx.x; e < 128 * 16; e += 256) {
        int r = e >> 4, sp = e & 15;
        cs[r][sp] = Ci[r * 128 + s0 + sp];
    }
    __syncthreads();

    const float* Nb = N + (size_t)b * R_DIM * W_DIM;
    float acc[16];
#pragma unroll
    for (int s = 0; s < 16; s++) acc[s] = 0.f;
    for (int r = 0; r < 128; r++) {
        float nv = Nb[(size_t)r * W_DIM + w];
#pragma unroll
        for (int s = 0; s < 16; s++) acc[s] += cs[r][s] * nv;
    }
    float g2 = 2.0f * gamma[b];
    float* Pt = g_Pt + (size_t)b * R_DIM * W_DIM;
#pragma unroll
    for (int s = 0; s < 16; s++)
        Pt[(size_t)(s0 + s) * W_DIM + w] = g2 * acc[s];
}

// ---------------------------------------------------------------------------
// K4: out[b][h][s] = sum_w A[b][h][w] * Pt[b][s][w]
// M=4096 (BM=256, single wave of 128 blocks), N=128, K=4096.
// 3xTF32 split MMA for fp32-grade accuracy. cp.async 3-stage pipeline.
// ---------------------------------------------------------------------------
#define BM 256
#define BN 128
#define BK 32
#define NSTAGE 3
#define NTHREADS 512
#define APAD 36                   // floats per smem row (pad vs 32)
#define ASZ (BM * APAD)           // floats
#define BSZ (BN * APAD)
#define STAGEF (ASZ + BSZ)        // floats per stage

__device__ __forceinline__ uint32_t smem_u32(const void* p) {
    return (uint32_t)__cvta_generic_to_shared(p);
}
__device__ __forceinline__ void cp_async16(uint32_t saddr, const float* g) {
    asm volatile("cp.async.cg.shared.global [%0], [%1], 16;" :: "r"(saddr), "l"(g) : "memory");
}
__device__ __forceinline__ uint32_t f32_tf32(uint32_t x) {
    uint32_t r;
    asm("cvt.rna.tf32.f32 %0, %1;" : "=r"(r) : "f"(__uint_as_float(x)));
    return r;
}
// x = hi + lo in tf32 pieces: hi = tf32(x), lo = tf32(x - hi)
__device__ __forceinline__ void split_tf32(uint32_t x, uint32_t& hi, uint32_t& lo) {
    uint32_t h = f32_tf32(x);
    float lof = __uint_as_float(x) - __uint_as_float(h);
    hi = h;
    lo = f32_tf32(__float_as_uint(lof));
}
__device__ __forceinline__ void mma_tf32(float* d, const uint32_t* a, const uint32_t* b) {
    asm volatile(
        "mma.sync.aligned.m16n8k8.row.col.f32.tf32.tf32.f32 "
        "{%0,%1,%2,%3}, {%4,%5,%6,%7}, {%8,%9}, {%0,%1,%2,%3};"
        : "+f"(d[0]), "+f"(d[1]), "+f"(d[2]), "+f"(d[3])
        : "r"(a[0]), "r"(a[1]), "r"(a[2]), "r"(a[3]),
          "r"(b[0]), "r"(b[1]));
}

__global__ void __launch_bounds__(NTHREADS, 1) k4_gemm(const float* __restrict__ A, float* __restrict__ O) {
    extern __shared__ float sm[];
    int b  = blockIdx.y;
    int m0 = blockIdx.x * BM;
    int tid = threadIdx.x;
    int lane = tid & 31, wid = tid >> 5;
    int wm = wid & 3;        // 4 warps in M -> 64 rows each
    int wn = wid >> 2;       // 4 warps in N -> 32 cols each

    const float* Ab = A + (size_t)b * H_DIM * W_DIM;
    const float* Bb = g_Pt + (size_t)b * R_DIM * W_DIM;

    float acc[4][4][4];
#pragma unroll
    for (int mt = 0; mt < 4; mt++)
#pragma unroll
        for (int nt = 0; nt < 4; nt++)
#pragma unroll
            for (int r = 0; r < 4; r++) acc[mt][nt][r] = 0.f;

    auto issue = [&](int stage, int kk) {
        float* base = sm + stage * STAGEF;
        // A tile: 256 rows x 32 floats = 2048 vec4
#pragma unroll
        for (int i = 0; i < 4; i++) {
            int c = tid + i * NTHREADS;
            int row = c >> 3, kc = c & 7;
            cp_async16(smem_u32(base + row * APAD + kc * 4),
                       Ab + (size_t)(m0 + row) * W_DIM + kk + kc * 4);
        }
        // B tile: 128 rows x 32 floats = 1024 vec4
#pragma unroll
        for (int i = 0; i < 2; i++) {
            int c = tid + i * NTHREADS;
            int row = c >> 3, kc = c & 7;
            cp_async16(smem_u32(base + ASZ + row * APAD + kc * 4),
                       Bb + (size_t)row * W_DIM + kk + kc * 4);
        }
        asm volatile("cp.async.commit_group;" ::: "memory");
    };

    issue(0, 0);
    issue(1, BK);

    const int KITERS = W_DIM / BK; // 128
    for (int kb = 0; kb < KITERS; kb++) {
        asm volatile("cp.async.wait_group 1;" ::: "memory");
        __syncthreads();
        const float* As = sm + (kb % NSTAGE) * STAGEF;
        const float* Bs = As + ASZ;

#pragma unroll
        for (int ksx = 0; ksx < 4; ksx++) {
            // --- B fragments: 4 nt-tiles of 16x8, split hi/lo ---
            uint32_t bhi[4][2], blo[4][2];
#pragma unroll
            for (int h = 0; h < 2; h++) {
                int nrow = wn * 32 + h * 16 + ((lane >> 4) << 3) + (lane & 7);
                uint32_t addr = smem_u32(Bs + nrow * APAD + ksx * 8) + ((lane >> 3) & 1) * 16;
                uint32_t r0, r1, r2, r3;
                asm volatile("ldmatrix.sync.aligned.m8n8.x4.shared.b16 {%0,%1,%2,%3}, [%4];"
                             : "=r"(r0), "=r"(r1), "=r"(r2), "=r"(r3) : "r"(addr));
                split_tf32(r0, bhi[2 * h][0],     blo[2 * h][0]);
                split_tf32(r1, bhi[2 * h][1],     blo[2 * h][1]);
                split_tf32(r2, bhi[2 * h + 1][0], blo[2 * h + 1][0]);
                split_tf32(r3, bhi[2 * h + 1][1], blo[2 * h + 1][1]);
            }
            // --- A fragments per mt, split, 3 MMAs per (mt,nt) ---
#pragma unroll
            for (int mt = 0; mt < 4; mt++) {
                int row = wm * 64 + mt * 16 + (lane & 15);
                uint32_t addr = smem_u32(As + row * APAD + ksx * 8) + (lane >> 4) * 16;
                uint32_t a0, a1, a2, a3;
                asm volatile("ldmatrix.sync.aligned.m8n8.x4.shared.b16 {%0,%1,%2,%3}, [%4];"
                             : "=r"(a0), "=r"(a1), "=r"(a2), "=r"(a3) : "r"(addr));
                uint32_t ahi[4], alo[4];
                split_tf32(a0, ahi[0], alo[0]);
                split_tf32(a1, ahi[1], alo[1]);
                split_tf32(a2, ahi[2], alo[2]);
                split_tf32(a3, ahi[3], alo[3]);
#pragma unroll
                for (int nt = 0; nt < 4; nt++) {
                    mma_tf32(acc[mt][nt], alo, bhi[nt]);   // lo*hi
                    mma_tf32(acc[mt][nt], ahi, blo[nt]);   // hi*lo
                    mma_tf32(acc[mt][nt], ahi, bhi[nt]);   // hi*hi
                }
            }
        }

        int nk = kb + 2;
        if (nk < KITERS) issue(nk % NSTAGE, nk * BK);
    }

    // Epilogue: direct float2 stores
#pragma unroll
    for (int mt = 0; mt < 4; mt++) {
#pragma unroll
        for (int nt = 0; nt < 4; nt++) {
            int r = m0 + wm * 64 + mt * 16 + (lane >> 2);
            int c = wn * 32 + nt * 8 + (lane & 3) * 2;
            float2 v0 = make_float2(acc[mt][nt][0], acc[mt][nt][1]);
            float2 v1 = make_float2(acc[mt][nt][2], acc[mt][nt][3]);
            *(float2*)(O + ((size_t)b * H_DIM + r) * R_DIM + c)       = v0;
            *(float2*)(O + ((size_t)b * H_DIM + r + 8) * R_DIM + c)   = v1;
        }
    }
}

// ---------------------------------------------------------------------------
extern "C" void kernel_launch(void* const* d_in, const int* in_sizes, int n_in,
                              void* d_out, int out_size) {
    (void)in_sizes; (void)n_in; (void)out_size;
    const float* N     = (const float*)d_in[0];
    const float* A     = (const float*)d_in[1];
    const float* alpha = (const float*)d_in[2];
    const float* gamma = (const float*)d_in[3];
    float* out = (float*)d_out;

    cudaFuncSetAttribute(k2_inv, cudaFuncAttributeMaxDynamicSharedMemorySize,
                         (128 * 129 + 256) * 4);
    cudaFuncSetAttribute(k4_gemm, cudaFuncAttributeMaxDynamicSharedMemorySize,
                         NSTAGE * STAGEF * 4);

    dim3 g1(16, KSPLIT, B_DIM), b1(16, 16);
    k1_gram<<<g1, b1>>>(N);

    k2_inv<<<B_DIM, 1024, (128 * 129 + 256) * 4>>>(alpha, gamma);

    dim3 g3(W_DIM / 256, R_DIM / 16, B_DIM);
    k3_pt<<<g3, 256>>>(N, gamma);

    dim3 g4(H_DIM / BM, B_DIM);
    k4_gemm<<<g4, NTHREADS, NSTAGE * STAGEF * 4>>>(A, out);
}

// round 4
// speedup vs baseline: 1.5130x; 1.5130x over previous
#include <cuda_runtime.h>
#include <cuda_fp16.h>
#include <cstdint>

#define B_DIM 8
#define R_DIM 128
#define H_DIM 4096
#define W_DIM 4096
#define KSPLIT 4

// Scratch (device globals: allocation-free per harness rules)
__device__ float  g_part[KSPLIT * B_DIM * R_DIM * R_DIM]; // 2 MB partial Gram
__device__ float  g_Ci[B_DIM * R_DIM * R_DIM];            // 512KB C^-1
__device__ __half g_Pth[B_DIM * R_DIM * W_DIM];           // 8 MB Pt hi (fp16)
__device__ __half g_Ptl[B_DIM * R_DIM * W_DIM];           // 8 MB Pt lo (fp16)

// ---------------------------------------------------------------------------
// K1: partial Gram  part[ks][b][r][s] = sum_{w in split} N[r][w]*N[s][w]
// ---------------------------------------------------------------------------
__global__ void k1_gram(const float* __restrict__ N) {
    __shared__ float As[32][33];
    __shared__ float Bs[32][33];
    int b  = blockIdx.z;
    int ks = blockIdx.y;
    int ti = blockIdx.x & 3, tj = blockIdx.x >> 2;
    int r0 = ti * 32, s0 = tj * 32;
    int tx = threadIdx.x, ty = threadIdx.y;
    int tid = ty * 16 + tx;
    const float* Nb = N + (size_t)b * R_DIM * W_DIM;

    float a00 = 0.f, a01 = 0.f, a10 = 0.f, a11 = 0.f;
    int k_beg = ks * (W_DIM / KSPLIT);
    int k_end = k_beg + (W_DIM / KSPLIT);
    for (int kk = k_beg; kk < k_end; kk += 32) {
        for (int e = tid; e < 1024; e += 256) {
            int i = e >> 5, k = e & 31;
            As[i][k] = Nb[(size_t)(r0 + i) * W_DIM + kk + k];
            Bs[i][k] = Nb[(size_t)(s0 + i) * W_DIM + kk + k];
        }
        __syncthreads();
#pragma unroll
        for (int k = 0; k < 32; k++) {
            float x0 = As[2 * ty][k], x1 = As[2 * ty + 1][k];
            float y0 = Bs[2 * tx][k], y1 = Bs[2 * tx + 1][k];
            a00 += x0 * y0; a01 += x0 * y1; a10 += x1 * y0; a11 += x1 * y1;
        }
        __syncthreads();
    }
    float* P = g_part + ((size_t)(ks * B_DIM + b)) * R_DIM * R_DIM;
    P[(r0 + 2 * ty) * 128 + s0 + 2 * tx]         = a00;
    P[(r0 + 2 * ty) * 128 + s0 + 2 * tx + 1]     = a01;
    P[(r0 + 2 * ty + 1) * 128 + s0 + 2 * tx]     = a10;
    P[(r0 + 2 * ty + 1) * 128 + s0 + 2 * tx + 1] = a11;
}

// ---------------------------------------------------------------------------
// K2: C = alpha*I + 2*gamma*G; REGISTER-RESIDENT Gauss-Jordan inverse.
// 1024 threads: thread t owns row i=t>>3, 16 cols starting jc=(t&7)*16.
// Only pivot row/col go through smem (double-buffered), 1 barrier per step.
// ---------------------------------------------------------------------------
__global__ void __launch_bounds__(1024, 1) k2_inv(const float* __restrict__ alpha,
                                                  const float* __restrict__ gamma) {
    __shared__ float s_rowk[2][128];
    __shared__ float s_colk[2][128];
    __shared__ float s_invp[2];

    int b = blockIdx.x;
    int t = threadIdx.x;
    int i  = t >> 3;
    int jc = (t & 7) << 4;
    float a  = alpha[b];
    float g2 = 2.0f * gamma[b];

    float M[16];
#pragma unroll
    for (int q = 0; q < 16; q++) {
        int e = i * 128 + jc + q;
        float s = 0.f;
#pragma unroll
        for (int p = 0; p < KSPLIT; p++)
            s += g_part[((size_t)(p * B_DIM + b)) * 16384 + e];
        M[q] = g2 * s + ((jc + q) == i ? a : 0.f);
    }
    // seed buffers for k=0
    if (i == 0) {
#pragma unroll
        for (int q = 0; q < 16; q++) s_rowk[0][jc + q] = M[q];
        if (jc == 0) s_invp[0] = 1.0f / M[0];
    }
    if (jc == 0) s_colk[0][i] = M[0];
    __syncthreads();

    for (int k = 0; k < 128; k++) {
        int par = k & 1;
        float ip = s_invp[par];
        if (i == k) {
#pragma unroll
            for (int q = 0; q < 16; q++) M[q] *= ip;
            if (k >= jc && k < jc + 16) M[k - jc] = ip;
        } else {
            float c = s_colk[par][i] * ip;
#pragma unroll
            for (int q = 0; q < 16; q++)
                M[q] = fmaf(-c, s_rowk[par][jc + q], M[q]);
            if (k >= jc && k < jc + 16) M[k - jc] = -c;
        }
        int kn = k + 1;
        if (kn < 128) {
            int pn = kn & 1;
            if (i == kn) {
#pragma unroll
                for (int q = 0; q < 16; q++) s_rowk[pn][jc + q] = M[q];
                if (kn >= jc && kn < jc + 16) s_invp[pn] = 1.0f / M[kn - jc];
            }
            if (kn >= jc && kn < jc + 16) s_colk[pn][i] = M[kn - jc];
        }
        __syncthreads();
    }

    float* Ci = g_Ci + (size_t)b * 16384;
#pragma unroll
    for (int q = 0; q < 16; q++)
        Ci[i * 128 + jc + q] = M[q];
}

// ---------------------------------------------------------------------------
// K3: Pt[b][s][w] = 2*gamma * sum_r Cinv[r][s] * N[r][w], split to fp16 hi/lo.
// ---------------------------------------------------------------------------
__global__ void k3_pt(const float* __restrict__ N, const float* __restrict__ gamma) {
    __shared__ float cs[128][17];
    int b  = blockIdx.z;
    int s0 = blockIdx.y * 16;
    int w  = blockIdx.x * 256 + threadIdx.x;
    const float* Ci = g_Ci + (size_t)b * 16384;
    for (int e = threadIdx.x; e < 128 * 16; e += 256) {
        int r = e >> 4, sp = e & 15;
        cs[r][sp] = Ci[r * 128 + s0 + sp];
    }
    __syncthreads();

    const float* Nb = N + (size_t)b * R_DIM * W_DIM;
    float acc[16];
#pragma unroll
    for (int s = 0; s < 16; s++) acc[s] = 0.f;
    for (int r = 0; r < 128; r++) {
        float nv = Nb[(size_t)r * W_DIM + w];
#pragma unroll
        for (int s = 0; s < 16; s++) acc[s] += cs[r][s] * nv;
    }
    float g2 = 2.0f * gamma[b];
    __half* Ph = g_Pth + (size_t)b * R_DIM * W_DIM;
    __half* Pl = g_Ptl + (size_t)b * R_DIM * W_DIM;
#pragma unroll
    for (int s = 0; s < 16; s++) {
        float v = g2 * acc[s];
        __half h = __float2half_rn(v);
        __half l = __float2half_rn(v - __half2float(h));
        Ph[(size_t)(s0 + s) * W_DIM + w] = h;
        Pl[(size_t)(s0 + s) * W_DIM + w] = l;
    }
}

// ---------------------------------------------------------------------------
// K4: out[b][h][s] = sum_w A[b][h][w] * Pt[b][s][w]
// fp16 2-way split, 3x m16n8k16 HMMA with fp32 accum.
// A converted fp32->fp16(hi,lo) at smem-fill; B pre-split by K3.
// 2-stage register-staged pipeline (LDG -> STS), 2 barriers/iter.
// ---------------------------------------------------------------------------
#define BM 256
#define BN 128
#define BK 32
#define NTHREADS 512
#define RS 40                        // halves per smem row (80B, conflict-free)
#define AH_OFF 0
#define AL_OFF (256 * RS)            // 10240
#define BH_OFF (512 * RS)            // 20480
#define BL_OFF (640 * RS)            // 25600
#define BUF_H  (768 * RS)            // 30720 halves per stage

__device__ __forceinline__ uint32_t smem_u32(const void* p) {
    return (uint32_t)__cvta_generic_to_shared(p);
}
__device__ __forceinline__ void ldsm_x4(uint32_t addr, uint32_t& r0, uint32_t& r1,
                                        uint32_t& r2, uint32_t& r3) {
    asm volatile("ldmatrix.sync.aligned.m8n8.x4.shared.b16 {%0,%1,%2,%3}, [%4];"
                 : "=r"(r0), "=r"(r1), "=r"(r2), "=r"(r3) : "r"(addr));
}
__device__ __forceinline__ void mma_f16(float* d, const uint32_t* a, const uint32_t* b) {
    asm volatile(
        "mma.sync.aligned.m16n8k16.row.col.f32.f16.f16.f32 "
        "{%0,%1,%2,%3}, {%4,%5,%6,%7}, {%8,%9}, {%0,%1,%2,%3};"
        : "+f"(d[0]), "+f"(d[1]), "+f"(d[2]), "+f"(d[3])
        : "r"(a[0]), "r"(a[1]), "r"(a[2]), "r"(a[3]),
          "r"(b[0]), "r"(b[1]));
}
__device__ __forceinline__ void split_h(float f, __half& h, __half& l) {
    h = __float2half_rn(f);
    l = __float2half_rn(f - __half2float(h));
}

__global__ void __launch_bounds__(NTHREADS, 1) k4_gemm(const float* __restrict__ A,
                                                       float* __restrict__ O) {
    extern __shared__ __half smh[];
    int b  = blockIdx.y;
    int m0 = blockIdx.x * BM;
    int tid = threadIdx.x;
    int lane = tid & 31, wid = tid >> 5;
    int wm = wid & 3;        // 4 warps in M -> 64 rows each
    int wn = wid >> 2;       // 4 warps in N -> 32 cols each

    const float*  Ab  = A + (size_t)b * H_DIM * W_DIM;
    const __half* Bhg = g_Pth + (size_t)b * R_DIM * W_DIM;
    const __half* Blg = g_Ptl + (size_t)b * R_DIM * W_DIM;

    float acc[4][4][4];
#pragma unroll
    for (int mt = 0; mt < 4; mt++)
#pragma unroll
        for (int nt = 0; nt < 4; nt++)
#pragma unroll
            for (int r = 0; r < 4; r++) acc[mt][nt][r] = 0.f;

    // register staging
    float4 a4[4];
    uint4  bh4, bl4;
    int brow = tid >> 2, bhc = tid & 3;

    auto ldg_stage = [&](int kk) {
#pragma unroll
        for (int i = 0; i < 4; i++) {
            int v = tid + i * NTHREADS;
            int row = v >> 3, kc = v & 7;
            a4[i] = *(const float4*)(Ab + (size_t)(m0 + row) * W_DIM + kk + kc * 4);
        }
        bh4 = *(const uint4*)(Bhg + (size_t)brow * W_DIM + kk + bhc * 8);
        bl4 = *(const uint4*)(Blg + (size_t)brow * W_DIM + kk + bhc * 8);
    };
    auto sts_stage = [&](int bufsel) {
        __half* base = smh + bufsel * BUF_H;
#pragma unroll
        for (int i = 0; i < 4; i++) {
            int v = tid + i * NTHREADS;
            int row = v >> 3, kc = v & 7;
            __half hx, lx, hy, ly, hz, lz, hw, lw;
            split_h(a4[i].x, hx, lx);
            split_h(a4[i].y, hy, ly);
            split_h(a4[i].z, hz, lz);
            split_h(a4[i].w, hw, lw);
            __half2* ph = (__half2*)(base + AH_OFF + row * RS + kc * 4);
            ph[0] = __halves2half2(hx, hy);
            ph[1] = __halves2half2(hz, hw);
            __half2* pl = (__half2*)(base + AL_OFF + row * RS + kc * 4);
            pl[0] = __halves2half2(lx, ly);
            pl[1] = __halves2half2(lz, lw);
        }
        *(uint4*)(base + BH_OFF + brow * RS + bhc * 8) = bh4;
        *(uint4*)(base + BL_OFF + brow * RS + bhc * 8) = bl4;
    };

    ldg_stage(0);

    const int KITERS = W_DIM / BK; // 128
    for (int kb = 0; kb < KITERS; kb++) {
        sts_stage(kb & 1);
        __syncthreads();
        if (kb + 1 < KITERS) ldg_stage((kb + 1) * BK);

        uint32_t sbase = smem_u32(smh + (kb & 1) * BUF_H);

#pragma unroll
        for (int ks = 0; ks < 2; ks++) {
            // --- B fragments (hi & lo), 4 nt-tiles ---
            uint32_t bhi[4][2], blo[4][2];
            int idx = lane >> 3;
            int kboff = ks * 32 + (idx & 1) * 16;   // bytes within 64B k-chunk
#pragma unroll
            for (int h = 0; h < 2; h++) {
                int nrow = wn * 32 + h * 16 + (idx >> 1) * 8 + (lane & 7);
                uint32_t r0, r1, r2, r3;
                ldsm_x4(sbase + (BH_OFF + nrow * RS) * 2 + kboff, r0, r1, r2, r3);
                bhi[2 * h][0] = r0; bhi[2 * h][1] = r1;
                bhi[2 * h + 1][0] = r2; bhi[2 * h + 1][1] = r3;
                ldsm_x4(sbase + (BL_OFF + nrow * RS) * 2 + kboff, r0, r1, r2, r3);
                blo[2 * h][0] = r0; blo[2 * h][1] = r1;
                blo[2 * h + 1][0] = r2; blo[2 * h + 1][1] = r3;
            }
            // --- A fragments per mt (hi & lo), 3 MMAs per (mt,nt) ---
            int karow = ks * 32 + (lane >> 4) * 16; // bytes
#pragma unroll
            for (int mt = 0; mt < 4; mt++) {
                int arow = wm * 64 + mt * 16 + (lane & 15);
                uint32_t ah[4], al[4];
                ldsm_x4(sbase + (AH_OFF + arow * RS) * 2 + karow,
                        ah[0], ah[1], ah[2], ah[3]);
                ldsm_x4(sbase + (AL_OFF + arow * RS) * 2 + karow,
                        al[0], al[1], al[2], al[3]);
#pragma unroll
                for (int nt = 0; nt < 4; nt++) {
                    mma_f16(acc[mt][nt], al, bhi[nt]);   // lo*hi
                    mma_f16(acc[mt][nt], ah, blo[nt]);   // hi*lo
                    mma_f16(acc[mt][nt], ah, bhi[nt]);   // hi*hi
                }
            }
        }
        __syncthreads();
    }

    // Epilogue: direct float2 stores
#pragma unroll
    for (int mt = 0; mt < 4; mt++) {
#pragma unroll
        for (int nt = 0; nt < 4; nt++) {
            int r = m0 + wm * 64 + mt * 16 + (lane >> 2);
            int c = wn * 32 + nt * 8 + (lane & 3) * 2;
            float2 v0 = make_float2(acc[mt][nt][0], acc[mt][nt][1]);
            float2 v1 = make_float2(acc[mt][nt][2], acc[mt][nt][3]);
            *(float2*)(O + ((size_t)b * H_DIM + r) * R_DIM + c)     = v0;
            *(float2*)(O + ((size_t)b * H_DIM + r + 8) * R_DIM + c) = v1;
        }
    }
}

// ---------------------------------------------------------------------------
extern "C" void kernel_launch(void* const* d_in, const int* in_sizes, int n_in,
                              void* d_out, int out_size) {
    (void)in_sizes; (void)n_in; (void)out_size;
    const float* N     = (const float*)d_in[0];
    const float* A     = (const float*)d_in[1];
    const float* alpha = (const float*)d_in[2];
    const float* gamma = (const float*)d_in[3];
    float* out = (float*)d_out;

    cudaFuncSetAttribute(k4_gemm, cudaFuncAttributeMaxDynamicSharedMemorySize,
                         2 * BUF_H * (int)sizeof(__half));

    dim3 g1(16, KSPLIT, B_DIM), b1(16, 16);
    k1_gram<<<g1, b1>>>(N);

    k2_inv<<<B_DIM, 1024>>>(alpha, gamma);

    dim3 g3(W_DIM / 256, R_DIM / 16, B_DIM);
    k3_pt<<<g3, 256>>>(N, gamma);

    dim3 g4(H_DIM / BM, B_DIM);
    k4_gemm<<<g4, NTHREADS, 2 * BUF_H * (int)sizeof(__half)>>>(A, out);
}